// round 14
// baseline (speedup 1.0000x reference)
#include <cuda_runtime.h>
#include <cuda_fp16.h>
#include <cstdint>
#include <math.h>

// Problem constants
#define NB   32
#define NS   2048
#define ND   1024
#define BSR  65536      // NB*NS rows
#define T_M  128
#define T_N  128
#define T_K  32
#define NKT  32         // ND / T_K
#define NT_N 8          // 1024 / 128 N-tiles

// Device scratch (no dynamic allocation allowed)
__device__ float g_qw[NB * ND];
__device__ float g_scores_part[NT_N][BSR];
__device__ float g_ctx_part[8][NB * ND];
__device__ uint4 g_keys_h4[(size_t)BSR * ND / 8];   // keys as fp16, 128 MB
__device__ uint4 g_ua_h4[ND * ND / 8];              // Ua_w as fp16, 2 MB

// ---------------- smem layout for gemm kernel (bytes) ----------------
// Per stage: 4 private A stripes (4KB each, wid-indexed) + 2 shared B stripes
// (4KB each, wn-indexed) = 24KB. 64B rows, XOR chunk swizzle.
#define STG_BYTES 24576
#define NSTAGE   3
#define OFF_QW   (NSTAGE * STG_BYTES)      // 73728: 128 floats
#define OFF_VA   (OFF_QW + 512)
#define OFF_SC   (OFF_VA + 512)            // 256 floats
#define SMEM_BYTES (OFF_SC + 1024)         // 75776

__device__ __forceinline__ void mma_f16(float* d, const uint32_t* a, const uint32_t* b) {
    asm volatile(
        "mma.sync.aligned.m16n8k16.row.col.f32.f16.f16.f32 "
        "{%0,%1,%2,%3}, {%4,%5,%6,%7}, {%8,%9}, {%0,%1,%2,%3};"
        : "+f"(d[0]), "+f"(d[1]), "+f"(d[2]), "+f"(d[3])
        : "r"(a[0]), "r"(a[1]), "r"(a[2]), "r"(a[3]), "r"(b[0]), "r"(b[1]));
}

__device__ __forceinline__ void ldsm_x4(uint32_t* r, uint32_t addr) {
    asm volatile("ldmatrix.sync.aligned.m8n8.x4.shared.b16 {%0,%1,%2,%3}, [%4];"
        : "=r"(r[0]), "=r"(r[1]), "=r"(r[2]), "=r"(r[3]) : "r"(addr));
}

__device__ __forceinline__ uint32_t pack2h(float x, float y) {
    __half2 h = __floats2half2_rn(x, y);
    return *(uint32_t*)&h;
}

// ---------------- Kernel A: fp32 -> fp16 converters ----------------
__global__ void cvt_kernel(const float4* __restrict__ src, uint4* __restrict__ dst) {
    size_t i = (size_t)blockIdx.x * blockDim.x + threadIdx.x;   // one uint4 = 8 halves
    float4 a = src[2 * i];
    float4 b = src[2 * i + 1];
    uint4 u;
    u.x = pack2h(a.x, a.y);
    u.y = pack2h(a.z, a.w);
    u.z = pack2h(b.x, b.y);
    u.w = pack2h(b.z, b.w);
    dst[i] = u;
}

// ---------------- Kernel 0: qW[b,n] = q[b] . Wa_w[n,:] + Wa_b[n] + Ua_b[n] ----------------
__global__ void qw_kernel(const float* __restrict__ query, const float* __restrict__ Wa_w,
                          const float* __restrict__ Wa_b, const float* __restrict__ Ua_b) {
    int b = blockIdx.x;
    int tid = threadIdx.x;                    // 128 threads
    int n = blockIdx.y * 128 + tid;
    __shared__ float4 qs[256];                // q[b] as 1024 floats
    for (int i = tid; i < 256; i += 128) {
        int k = i * 4;
        // q = concat(query[b,1,:], query[b,3,:]); query is (B,4,512)
        const float* src = (k < 512) ? (query + (size_t)b * 2048 + 512 + k)
                                     : (query + (size_t)b * 2048 + 1024 + k);
        qs[i] = *(const float4*)src;
    }
    __syncthreads();
    const float4* wr = (const float4*)(Wa_w + (size_t)n * ND);
    float acc = 0.f;
    #pragma unroll 8
    for (int i = 0; i < 256; i++) {
        float4 a = qs[i], w = wr[i];
        acc += a.x * w.x + a.y * w.y + a.z * w.z + a.w * w.w;
    }
    g_qw[b * ND + n] = acc + Wa_b[n] + Ua_b[n];
}

// ---------------- Kernel 1: fp16 mma GEMM, warp-autonomous + pair-shared B ----------------
// 128x128 CTA, 4 warps of 64x64, 2 CTA/SM. Each warp loads its own A stripe and
// HALF of the B stripe shared with its pair partner (same wn). One named
// bar.sync(1+wn, 64) per tile; no CTA-wide barriers in the mainloop.
__global__ void __launch_bounds__(128, 2)
gemm_score_kernel(const float* __restrict__ Va_w) {
    extern __shared__ __align__(16) char smc[];
    float* qw_s = (float*)(smc + OFF_QW);
    float* va_s = (float*)(smc + OFF_VA);
    float* sc_s = (float*)(smc + OFF_SC);

    const __half* keys_h = (const __half*)g_keys_h4;
    const __half* ua_h   = (const __half*)g_ua_h4;

    const int tid = threadIdx.x;              // 128 threads, 4 warps
    const int wid = tid >> 5;
    const int lane = tid & 31;
    const int r = lane >> 2;                  // 0..7
    const int c = lane & 3;                   // 0..3
    const int wm = wid & 1;                   // 2 warps along M (64 rows each)
    const int wn = wid >> 1;                  // 2 warps along N (64 cols each)

    const int nt = blockIdx.x;                // N-tile (fast dim -> A reuse in L2)
    const int n0 = nt * T_N;
    const int m0 = blockIdx.y * T_M;
    const int b  = blockIdx.y >> 4;           // 16 M-tiles of 128 per batch

    const uint32_t sbase = (uint32_t)__cvta_generic_to_shared(smc);

    // global stripe bases
    const __half* agl = keys_h + (size_t)(m0 + wm * 64) * ND;       // private A
    const __half* bgl = ua_h + (size_t)(n0 + wn * 64) * ND;         // shared-B stripe

    // loader: A = 256 chunks (8/lane), B-half = 128 chunks (4/lane), 16B each
    // chunk j: row = j>>2, c0 = j&3; smem chunk = c0 ^ ((row>>1)&3)
    auto load_tile = [&](int kt, int s) {
        uint32_t stg = sbase + s * STG_BYTES;
        uint32_t wa = stg + wid * 4096;                    // private A stripe
        uint32_t wbv = stg + 16384 + wn * 4096;            // shared B stripe
        const __half* asrc = agl + (size_t)kt * T_K;
        const __half* bsrc = bgl + (size_t)kt * T_K;
        #pragma unroll
        for (int i = 0; i < 8; i++) {
            int j = lane + i * 32;
            int row = j >> 2, c0 = j & 3;
            int ch = c0 ^ ((row >> 1) & 3);
            asm volatile("cp.async.cg.shared.global [%0], [%1], 16;"
                :: "r"(wa + (uint32_t)(row * 64 + ch * 16)),
                   "l"(asrc + (size_t)row * ND + c0 * 8));
        }
        #pragma unroll
        for (int i = 0; i < 4; i++) {
            int j = lane + i * 32;
            int rl = (j >> 2) + wm * 32, c0 = j & 3;       // this warp's half rows
            int ch = c0 ^ ((rl >> 1) & 3);
            asm volatile("cp.async.cg.shared.global [%0], [%1], 16;"
                :: "r"(wbv + (uint32_t)(rl * 64 + ch * 16)),
                   "l"(bsrc + (size_t)rl * ND + c0 * 8));
        }
        asm volatile("cp.async.commit_group;");
    };

    // ldmatrix lane geometry (A): lanes 0-15 -> rows 0-15, lanes 16-31 -> k+16B
    const int frow_a = lane & 15;
    const int kh_a   = lane >> 4;
    const int sw_a   = (frow_a >> 1) & 3;
    // ldmatrix lane geometry (B): {0-7,8-15,16-23,24-31} -> {n0-7/k0, n0-7/k1, n8-15/k0, n8-15/k1}
    const int frow_b = ((lane >> 4) << 3) + (lane & 7);
    const int kh_b   = (lane >> 3) & 1;
    const int sw_b   = (frow_b >> 1) & 3;

    for (int j = tid; j < T_N; j += 128) {
        qw_s[j] = g_qw[b * ND + n0 + j];
        va_s[j] = Va_w[n0 + j];
    }
    __syncthreads();                          // qw/va visible before any warp's epilogue

    load_tile(0, 0);
    load_tile(1, 1);
    load_tile(2, 2);

    float acc[4][8][4];
    #pragma unroll
    for (int im = 0; im < 4; im++)
        #pragma unroll
        for (int in = 0; in < 8; in++)
            #pragma unroll
            for (int k = 0; k < 4; k++) acc[im][in][k] = 0.f;

    for (int kt = 0; kt < NKT; kt++) {
        const int s = kt % NSTAGE;
        // tiles kt and kt+1 landed (partner's B(kt) visibility: partner waited
        // for kt at its tile kt-1 top, then both crossed bar_b(kt-1))
        if (kt + 1 < NKT) { asm volatile("cp.async.wait_group 1;"); }
        else              { asm volatile("cp.async.wait_group 0;"); }
        __syncwarp();

        const uint32_t stg = sbase + s * STG_BYTES;
        const uint32_t wa = stg + wid * 4096;
        const uint32_t wbv = stg + 16384 + wn * 4096;

        // ---- ks = 0: LDSM + MMA ----
        uint32_t afr[4][4], bfr[4][4];
        #pragma unroll
        for (int im = 0; im < 4; im++)
            ldsm_x4(afr[im], wa + (uint32_t)((im * 16 + frow_a) * 64 + (kh_a ^ sw_a) * 16));
        #pragma unroll
        for (int ip = 0; ip < 4; ip++)
            ldsm_x4(bfr[ip], wbv + (uint32_t)((ip * 16 + frow_b) * 64 + (kh_b ^ sw_b) * 16));
        #pragma unroll
        for (int in = 0; in < 8; in++) {
            const uint32_t* bb = &bfr[in >> 1][(in & 1) * 2];
            #pragma unroll
            for (int im = 0; im < 4; im++)
                mma_f16(acc[im][in], afr[im], bb);
        }

        // ---- ks = 1: LDSM, then pair barrier, then reload stage, then MMA ----
        uint32_t afr2[4][4], bfr2[4][4];
        #pragma unroll
        for (int im = 0; im < 4; im++)
            ldsm_x4(afr2[im], wa + (uint32_t)((im * 16 + frow_a) * 64 + ((2 + kh_a) ^ sw_a) * 16));
        #pragma unroll
        for (int ip = 0; ip < 4; ip++)
            ldsm_x4(bfr2[ip], wbv + (uint32_t)((ip * 16 + frow_b) * 64 + ((2 + kh_b) ^ sw_b) * 16));

        // pair barrier: both partners done reading stage s; safe to overwrite
        asm volatile("bar.sync %0, %1;" :: "r"(1 + wn), "r"(64) : "memory");
        if (kt + 3 < NKT)
            load_tile(kt + 3, s);

        #pragma unroll
        for (int in = 0; in < 8; in++) {
            const uint32_t* bb = &bfr2[in >> 1][(in & 1) * 2];
            #pragma unroll
            for (int im = 0; im < 4; im++)
                mma_f16(acc[im][in], afr2[im], bb);
        }
    }

    // Epilogue: score_part[m] = sum_n Va[n] * tanh(acc[m][n] + qw[n]) over this CTA's 128 n
    #pragma unroll
    for (int im = 0; im < 4; im++) {
        float rs0 = 0.f, rs1 = 0.f;
        #pragma unroll
        for (int in = 0; in < 8; in++) {
            int col0 = wn * 64 + in * 8 + 2 * c;
            float v0 = va_s[col0],     q0 = qw_s[col0];
            float v1 = va_s[col0 + 1], q1 = qw_s[col0 + 1];
            rs0 += v0 * tanhf(acc[im][in][0] + q0) + v1 * tanhf(acc[im][in][1] + q1);
            rs1 += v0 * tanhf(acc[im][in][2] + q0) + v1 * tanhf(acc[im][in][3] + q1);
        }
        // reduce the 4 lanes sharing each row (lane^1, lane^2 stay in the quad)
        rs0 += __shfl_xor_sync(0xffffffffu, rs0, 1);
        rs0 += __shfl_xor_sync(0xffffffffu, rs0, 2);
        rs1 += __shfl_xor_sync(0xffffffffu, rs1, 1);
        rs1 += __shfl_xor_sync(0xffffffffu, rs1, 2);
        if (c == 0) {
            int rowb = wm * 64 + im * 16 + r;
            sc_s[wn * 128 + rowb] = rs0;
            sc_s[wn * 128 + rowb + 8] = rs1;
        }
    }
    __syncthreads();
    g_scores_part[nt][m0 + tid] = sc_s[tid] + sc_s[128 + tid];
}

// ---------------- Kernel 2: softmax over S per batch, writes weights output ----------------
__global__ void softmax_kernel(float* __restrict__ wts) {
    int b = blockIdx.x;
    int tid = threadIdx.x;                    // 256 threads
    __shared__ float red[8];
    float v[8];
    float mx = -1e30f;
    #pragma unroll
    for (int i = 0; i < 8; i++) {
        int s = tid + i * 256;
        float x = 0.f;
        #pragma unroll
        for (int t = 0; t < NT_N; t++) x += g_scores_part[t][b * NS + s];
        v[i] = x;
        mx = fmaxf(mx, x);
    }
    #pragma unroll
    for (int o = 16; o; o >>= 1) mx = fmaxf(mx, __shfl_xor_sync(0xffffffffu, mx, o));
    if ((tid & 31) == 0) red[tid >> 5] = mx;
    __syncthreads();
    float bm = red[0];
    #pragma unroll
    for (int i = 1; i < 8; i++) bm = fmaxf(bm, red[i]);
    __syncthreads();
    float sum = 0.f;
    #pragma unroll
    for (int i = 0; i < 8; i++) { v[i] = __expf(v[i] - bm); sum += v[i]; }
    #pragma unroll
    for (int o = 16; o; o >>= 1) sum += __shfl_xor_sync(0xffffffffu, sum, o);
    if ((tid & 31) == 0) red[tid >> 5] = sum;
    __syncthreads();
    float bs = 0.f;
    #pragma unroll
    for (int i = 0; i < 8; i++) bs += red[i];
    float inv = 1.0f / bs;
    #pragma unroll
    for (int i = 0; i < 8; i++) wts[b * NS + tid + i * 256] = v[i] * inv;
}

// ---------------- Kernel 3: context partials from fp16 keys (halved traffic) ----------------
__global__ void ctx_part_kernel(const float* __restrict__ wts) {
    const __half* keys_h = (const __half*)g_keys_h4;
    int b = blockIdx.x;
    int d = blockIdx.y * 128 + threadIdx.x;
    int z = blockIdx.z;
    int s0 = z * 256;
    __shared__ float ws[256];
    for (int i = threadIdx.x; i < 256; i += 128) ws[i] = wts[b * NS + s0 + i];
    __syncthreads();
    const __half* kp = keys_h + ((size_t)(b * NS + s0)) * ND + d;
    float acc = 0.f;
    #pragma unroll 8
    for (int s = 0; s < 256; s++) acc += ws[s] * __half2float(kp[(size_t)s * ND]);
    g_ctx_part[z][b * ND + d] = acc;
}

// ---------------- Kernel 4: reduce context partials -> output ----------------
__global__ void ctx_reduce_kernel(float* __restrict__ ctx) {
    int b = blockIdx.x;
    int d = threadIdx.x;                      // 1024 threads
    float a = 0.f;
    #pragma unroll
    for (int z = 0; z < 8; z++) a += g_ctx_part[z][b * ND + d];
    ctx[b * ND + d] = a;
}

// ---------------- launch ----------------
extern "C" void kernel_launch(void* const* d_in, const int* in_sizes, int n_in,
                              void* d_out, int out_size) {
    const float* query = (const float*)d_in[0];
    const float* keys  = (const float*)d_in[1];
    const float* Wa_w  = (const float*)d_in[2];
    const float* Wa_b  = (const float*)d_in[3];
    const float* Ua_w  = (const float*)d_in[4];
    const float* Ua_b  = (const float*)d_in[5];
    const float* Va_w  = (const float*)d_in[6];
    // Va_b (d_in[7]) cancels in softmax; scores are not an output.

    float* out = (float*)d_out;
    float* ctx = out;                                  // (B,1,2H) = 32768 floats
    float* wts = (out_size >= NB * ND + NB * NS) ? out + NB * ND : out;  // (B,1,S)

    uint4* keys_h4;  cudaGetSymbolAddress((void**)&keys_h4, g_keys_h4);
    uint4* ua_h4;    cudaGetSymbolAddress((void**)&ua_h4, g_ua_h4);

    cudaFuncSetAttribute(gemm_score_kernel, cudaFuncAttributeMaxDynamicSharedMemorySize, SMEM_BYTES);

    cvt_kernel<<<(size_t)BSR * ND / 8 / 256, 256>>>((const float4*)keys, keys_h4);
    cvt_kernel<<<ND * ND / 8 / 256, 256>>>((const float4*)Ua_w, ua_h4);
    qw_kernel<<<dim3(NB, 8), 128>>>(query, Wa_w, Wa_b, Ua_b);
    gemm_score_kernel<<<dim3(NT_N, BSR / T_M), 128, SMEM_BYTES>>>(Va_w);
    softmax_kernel<<<NB, 256>>>(wts);
    ctx_part_kernel<<<dim3(NB, 8, 8), 128>>>(wts);
    ctx_reduce_kernel<<<NB, 1024>>>(ctx);
}

// round 15
// speedup vs baseline: 1.0419x; 1.0419x over previous
#include <cuda_runtime.h>
#include <cuda_fp16.h>
#include <cstdint>
#include <math.h>

// Problem constants
#define NB   32
#define NS   2048
#define ND   1024
#define BSR  65536      // NB*NS rows
#define T_M  128
#define T_N  128
#define T_K  32
#define NKT  32         // ND / T_K
#define NT_N 8          // 1024 / 128 N-tiles

// Device scratch (no dynamic allocation allowed)
__device__ float g_qw[NB * ND];
__device__ float g_scores_part[NT_N][BSR];
__device__ float g_ctx_part[8][NB * ND];
__device__ uint4 g_keys_h4[(size_t)BSR * ND / 8];   // keys as fp16, 128 MB
__device__ uint4 g_ua_h4[ND * ND / 8];              // Ua_w as fp16, 2 MB
__device__ uint4 g_wa_h4[ND * ND / 8];              // Wa_w as fp16, 2 MB

// ---------------- smem layout for gemm kernel (bytes) ----------------
// Per stage: 4 private A stripes (4KB each, wid-indexed) + 2 shared B stripes
// (4KB each, wn-indexed) = 24KB. 64B rows, XOR chunk swizzle.
#define STG_BYTES 24576
#define NSTAGE   3
#define OFF_QW   (NSTAGE * STG_BYTES)      // 73728: 128 floats
#define OFF_VA   (OFF_QW + 512)
#define OFF_SC   (OFF_VA + 512)            // 256 floats
#define SMEM_BYTES (OFF_SC + 1024)         // 75776

__device__ __forceinline__ void mma_f16(float* d, const uint32_t* a, const uint32_t* b) {
    asm volatile(
        "mma.sync.aligned.m16n8k16.row.col.f32.f16.f16.f32 "
        "{%0,%1,%2,%3}, {%4,%5,%6,%7}, {%8,%9}, {%0,%1,%2,%3};"
        : "+f"(d[0]), "+f"(d[1]), "+f"(d[2]), "+f"(d[3])
        : "r"(a[0]), "r"(a[1]), "r"(a[2]), "r"(a[3]), "r"(b[0]), "r"(b[1]));
}

__device__ __forceinline__ void ldsm_x4(uint32_t* r, uint32_t addr) {
    asm volatile("ldmatrix.sync.aligned.m8n8.x4.shared.b16 {%0,%1,%2,%3}, [%4];"
        : "=r"(r[0]), "=r"(r[1]), "=r"(r[2]), "=r"(r[3]) : "r"(addr));
}

__device__ __forceinline__ uint32_t pack2h(float x, float y) {
    __half2 h = __floats2half2_rn(x, y);
    return *(uint32_t*)&h;
}

// ---------------- Kernel A: fp32 -> fp16 converter (64B read / 32B write per thread) ----------------
__global__ void cvt_kernel(const float4* __restrict__ src, uint4* __restrict__ dst) {
    size_t i = (size_t)blockIdx.x * blockDim.x + threadIdx.x;
    float4 a = src[4 * i];
    float4 b = src[4 * i + 1];
    float4 e = src[4 * i + 2];
    float4 f = src[4 * i + 3];
    uint4 u, v;
    u.x = pack2h(a.x, a.y);  u.y = pack2h(a.z, a.w);
    u.z = pack2h(b.x, b.y);  u.w = pack2h(b.z, b.w);
    v.x = pack2h(e.x, e.y);  v.y = pack2h(e.z, e.w);
    v.z = pack2h(f.x, f.y);  v.w = pack2h(f.z, f.w);
    dst[2 * i] = u;
    dst[2 * i + 1] = v;
}

// ---------------- Kernel 0: qW[b,n] = q[b] . Wa_w[n,:] + Wa_b[n] + Ua_b[n] (fp16 Wa) ----------------
__global__ void qw_kernel(const float* __restrict__ query,
                          const float* __restrict__ Wa_b, const float* __restrict__ Ua_b) {
    const __half* wa_h = (const __half*)g_wa_h4;
    int b = blockIdx.x;
    int tid = threadIdx.x;                    // 128 threads
    int n = blockIdx.y * 128 + tid;
    __shared__ float4 qs[256];                // q[b] as 1024 floats
    for (int i = tid; i < 256; i += 128) {
        int k = i * 4;
        // q = concat(query[b,1,:], query[b,3,:]); query is (B,4,512)
        const float* src = (k < 512) ? (query + (size_t)b * 2048 + 512 + k)
                                     : (query + (size_t)b * 2048 + 1024 + k);
        qs[i] = *(const float4*)src;
    }
    __syncthreads();
    const uint4* wr = (const uint4*)(wa_h + (size_t)n * ND);   // 128 x 8 halves
    float acc = 0.f;
    #pragma unroll 4
    for (int i = 0; i < 128; i++) {
        uint4 w = wr[i];
        float4 q0 = qs[2 * i], q1 = qs[2 * i + 1];
        float2 f0 = __half22float2(*(const __half2*)&w.x);
        float2 f1 = __half22float2(*(const __half2*)&w.y);
        float2 f2 = __half22float2(*(const __half2*)&w.z);
        float2 f3 = __half22float2(*(const __half2*)&w.w);
        acc += q0.x * f0.x + q0.y * f0.y + q0.z * f1.x + q0.w * f1.y
             + q1.x * f2.x + q1.y * f2.y + q1.z * f3.x + q1.w * f3.y;
    }
    g_qw[b * ND + n] = acc + Wa_b[n] + Ua_b[n];
}

// ---------------- Kernel 1: fp16 mma GEMM, warp-autonomous + pair-shared B ----------------
// 128x128 CTA, 4 warps of 64x64, 2 CTA/SM. Each warp loads its own A stripe and
// HALF of the B stripe shared with its pair partner (same wn). One named
// bar.sync(1+wn, 64) per tile; no CTA-wide barriers in the mainloop.
__global__ void __launch_bounds__(128, 2)
gemm_score_kernel(const float* __restrict__ Va_w) {
    extern __shared__ __align__(16) char smc[];
    float* qw_s = (float*)(smc + OFF_QW);
    float* va_s = (float*)(smc + OFF_VA);
    float* sc_s = (float*)(smc + OFF_SC);

    const __half* keys_h = (const __half*)g_keys_h4;
    const __half* ua_h   = (const __half*)g_ua_h4;

    const int tid = threadIdx.x;              // 128 threads, 4 warps
    const int wid = tid >> 5;
    const int lane = tid & 31;
    const int r = lane >> 2;                  // 0..7
    const int c = lane & 3;                   // 0..3
    const int wm = wid & 1;                   // 2 warps along M (64 rows each)
    const int wn = wid >> 1;                  // 2 warps along N (64 cols each)

    const int nt = blockIdx.x;                // N-tile (fast dim -> A reuse in L2)
    const int n0 = nt * T_N;
    const int m0 = blockIdx.y * T_M;
    const int b  = blockIdx.y >> 4;           // 16 M-tiles of 128 per batch

    const uint32_t sbase = (uint32_t)__cvta_generic_to_shared(smc);

    // global stripe bases
    const __half* agl = keys_h + (size_t)(m0 + wm * 64) * ND;       // private A
    const __half* bgl = ua_h + (size_t)(n0 + wn * 64) * ND;         // shared-B stripe

    // loader: A = 256 chunks (8/lane), B-half = 128 chunks (4/lane), 16B each
    // chunk j: row = j>>2, c0 = j&3; smem chunk = c0 ^ ((row>>1)&3)
    auto load_tile = [&](int kt, int s) {
        uint32_t stg = sbase + s * STG_BYTES;
        uint32_t wa = stg + wid * 4096;                    // private A stripe
        uint32_t wbv = stg + 16384 + wn * 4096;            // shared B stripe
        const __half* asrc = agl + (size_t)kt * T_K;
        const __half* bsrc = bgl + (size_t)kt * T_K;
        #pragma unroll
        for (int i = 0; i < 8; i++) {
            int j = lane + i * 32;
            int row = j >> 2, c0 = j & 3;
            int ch = c0 ^ ((row >> 1) & 3);
            asm volatile("cp.async.cg.shared.global [%0], [%1], 16;"
                :: "r"(wa + (uint32_t)(row * 64 + ch * 16)),
                   "l"(asrc + (size_t)row * ND + c0 * 8));
        }
        #pragma unroll
        for (int i = 0; i < 4; i++) {
            int j = lane + i * 32;
            int rl = (j >> 2) + wm * 32, c0 = j & 3;       // this warp's half rows
            int ch = c0 ^ ((rl >> 1) & 3);
            asm volatile("cp.async.cg.shared.global [%0], [%1], 16;"
                :: "r"(wbv + (uint32_t)(rl * 64 + ch * 16)),
                   "l"(bsrc + (size_t)rl * ND + c0 * 8));
        }
        asm volatile("cp.async.commit_group;");
    };

    // ldmatrix lane geometry (A): lanes 0-15 -> rows 0-15, lanes 16-31 -> k+16B
    const int frow_a = lane & 15;
    const int kh_a   = lane >> 4;
    const int sw_a   = (frow_a >> 1) & 3;
    // ldmatrix lane geometry (B): {0-7,8-15,16-23,24-31} -> {n0-7/k0, n0-7/k1, n8-15/k0, n8-15/k1}
    const int frow_b = ((lane >> 4) << 3) + (lane & 7);
    const int kh_b   = (lane >> 3) & 1;
    const int sw_b   = (frow_b >> 1) & 3;

    for (int j = tid; j < T_N; j += 128) {
        qw_s[j] = g_qw[b * ND + n0 + j];
        va_s[j] = Va_w[n0 + j];
    }
    __syncthreads();                          // qw/va visible before any warp's epilogue

    load_tile(0, 0);
    load_tile(1, 1);
    load_tile(2, 2);

    float acc[4][8][4];
    #pragma unroll
    for (int im = 0; im < 4; im++)
        #pragma unroll
        for (int in = 0; in < 8; in++)
            #pragma unroll
            for (int k = 0; k < 4; k++) acc[im][in][k] = 0.f;

    for (int kt = 0; kt < NKT; kt++) {
        const int s = kt % NSTAGE;
        // tiles kt and kt+1 landed (partner's B(kt) visibility: partner waited
        // for kt at its tile kt-1 top, then both crossed bar_b(kt-1))
        if (kt + 1 < NKT) { asm volatile("cp.async.wait_group 1;"); }
        else              { asm volatile("cp.async.wait_group 0;"); }
        __syncwarp();

        const uint32_t stg = sbase + s * STG_BYTES;
        const uint32_t wa = stg + wid * 4096;
        const uint32_t wbv = stg + 16384 + wn * 4096;

        // ---- ks = 0: LDSM + MMA ----
        uint32_t afr[4][4], bfr[4][4];
        #pragma unroll
        for (int im = 0; im < 4; im++)
            ldsm_x4(afr[im], wa + (uint32_t)((im * 16 + frow_a) * 64 + (kh_a ^ sw_a) * 16));
        #pragma unroll
        for (int ip = 0; ip < 4; ip++)
            ldsm_x4(bfr[ip], wbv + (uint32_t)((ip * 16 + frow_b) * 64 + (kh_b ^ sw_b) * 16));
        #pragma unroll
        for (int in = 0; in < 8; in++) {
            const uint32_t* bb = &bfr[in >> 1][(in & 1) * 2];
            #pragma unroll
            for (int im = 0; im < 4; im++)
                mma_f16(acc[im][in], afr[im], bb);
        }

        // ---- ks = 1: LDSM, then pair barrier, then reload stage, then MMA ----
        uint32_t afr2[4][4], bfr2[4][4];
        #pragma unroll
        for (int im = 0; im < 4; im++)
            ldsm_x4(afr2[im], wa + (uint32_t)((im * 16 + frow_a) * 64 + ((2 + kh_a) ^ sw_a) * 16));
        #pragma unroll
        for (int ip = 0; ip < 4; ip++)
            ldsm_x4(bfr2[ip], wbv + (uint32_t)((ip * 16 + frow_b) * 64 + ((2 + kh_b) ^ sw_b) * 16));

        // pair barrier: both partners done reading stage s; safe to overwrite
        asm volatile("bar.sync %0, %1;" :: "r"(1 + wn), "r"(64) : "memory");
        if (kt + 3 < NKT)
            load_tile(kt + 3, s);

        #pragma unroll
        for (int in = 0; in < 8; in++) {
            const uint32_t* bb = &bfr2[in >> 1][(in & 1) * 2];
            #pragma unroll
            for (int im = 0; im < 4; im++)
                mma_f16(acc[im][in], afr2[im], bb);
        }
    }

    // Epilogue: score_part[m] = sum_n Va[n] * tanh(acc[m][n] + qw[n]) over this CTA's 128 n
    #pragma unroll
    for (int im = 0; im < 4; im++) {
        float rs0 = 0.f, rs1 = 0.f;
        #pragma unroll
        for (int in = 0; in < 8; in++) {
            int col0 = wn * 64 + in * 8 + 2 * c;
            float v0 = va_s[col0],     q0 = qw_s[col0];
            float v1 = va_s[col0 + 1], q1 = qw_s[col0 + 1];
            rs0 += v0 * tanhf(acc[im][in][0] + q0) + v1 * tanhf(acc[im][in][1] + q1);
            rs1 += v0 * tanhf(acc[im][in][2] + q0) + v1 * tanhf(acc[im][in][3] + q1);
        }
        // reduce the 4 lanes sharing each row (lane^1, lane^2 stay in the quad)
        rs0 += __shfl_xor_sync(0xffffffffu, rs0, 1);
        rs0 += __shfl_xor_sync(0xffffffffu, rs0, 2);
        rs1 += __shfl_xor_sync(0xffffffffu, rs1, 1);
        rs1 += __shfl_xor_sync(0xffffffffu, rs1, 2);
        if (c == 0) {
            int rowb = wm * 64 + im * 16 + r;
            sc_s[wn * 128 + rowb] = rs0;
            sc_s[wn * 128 + rowb + 8] = rs1;
        }
    }
    __syncthreads();
    g_scores_part[nt][m0 + tid] = sc_s[tid] + sc_s[128 + tid];
}

// ---------------- Kernel 2: softmax over S per batch, writes weights output ----------------
__global__ void softmax_kernel(float* __restrict__ wts) {
    int b = blockIdx.x;
    int tid = threadIdx.x;                    // 256 threads
    __shared__ float red[8];
    float v[8];
    float mx = -1e30f;
    #pragma unroll
    for (int i = 0; i < 8; i++) {
        int s = tid + i * 256;
        float x = 0.f;
        #pragma unroll
        for (int t = 0; t < NT_N; t++) x += g_scores_part[t][b * NS + s];
        v[i] = x;
        mx = fmaxf(mx, x);
    }
    #pragma unroll
    for (int o = 16; o; o >>= 1) mx = fmaxf(mx, __shfl_xor_sync(0xffffffffu, mx, o));
    if ((tid & 31) == 0) red[tid >> 5] = mx;
    __syncthreads();
    float bm = red[0];
    #pragma unroll
    for (int i = 1; i < 8; i++) bm = fmaxf(bm, red[i]);
    __syncthreads();
    float sum = 0.f;
    #pragma unroll
    for (int i = 0; i < 8; i++) { v[i] = __expf(v[i] - bm); sum += v[i]; }
    #pragma unroll
    for (int o = 16; o; o >>= 1) sum += __shfl_xor_sync(0xffffffffu, sum, o);
    if ((tid & 31) == 0) red[tid >> 5] = sum;
    __syncthreads();
    float bs = 0.f;
    #pragma unroll
    for (int i = 0; i < 8; i++) bs += red[i];
    float inv = 1.0f / bs;
    #pragma unroll
    for (int i = 0; i < 8; i++) wts[b * NS + tid + i * 256] = v[i] * inv;
}

// ---------------- Kernel 3: context partials from fp16 keys, half2 loads ----------------
__global__ void ctx_part_kernel(const float* __restrict__ wts) {
    const __half2* keys_h2 = (const __half2*)g_keys_h4;
    int b = blockIdx.x;
    int d2 = blockIdx.y * 128 + threadIdx.x;  // half2 index: dims 2*d2, 2*d2+1
    int z = blockIdx.z;
    int s0 = z * 256;
    __shared__ float ws[256];
    for (int i = threadIdx.x; i < 256; i += 128) ws[i] = wts[b * NS + s0 + i];
    __syncthreads();
    const __half2* kp = keys_h2 + ((size_t)(b * NS + s0)) * (ND / 2) + d2;
    float ax = 0.f, ay = 0.f;
    #pragma unroll 8
    for (int s = 0; s < 256; s++) {
        float2 f = __half22float2(kp[(size_t)s * (ND / 2)]);
        ax += ws[s] * f.x;
        ay += ws[s] * f.y;
    }
    float2* outp = (float2*)(&g_ctx_part[z][b * ND + 2 * d2]);
    *outp = make_float2(ax, ay);
}

// ---------------- Kernel 4: reduce context partials -> output ----------------
__global__ void ctx_reduce_kernel(float* __restrict__ ctx) {
    int b = blockIdx.x;
    int d = threadIdx.x;                      // 1024 threads
    float a = 0.f;
    #pragma unroll
    for (int z = 0; z < 8; z++) a += g_ctx_part[z][b * ND + d];
    ctx[b * ND + d] = a;
}

// ---------------- launch ----------------
extern "C" void kernel_launch(void* const* d_in, const int* in_sizes, int n_in,
                              void* d_out, int out_size) {
    const float* query = (const float*)d_in[0];
    const float* keys  = (const float*)d_in[1];
    const float* Wa_w  = (const float*)d_in[2];
    const float* Wa_b  = (const float*)d_in[3];
    const float* Ua_w  = (const float*)d_in[4];
    const float* Ua_b  = (const float*)d_in[5];
    const float* Va_w  = (const float*)d_in[6];
    // Va_b (d_in[7]) cancels in softmax; scores are not an output.

    float* out = (float*)d_out;
    float* ctx = out;                                  // (B,1,2H) = 32768 floats
    float* wts = (out_size >= NB * ND + NB * NS) ? out + NB * ND : out;  // (B,1,S)

    uint4* keys_h4;  cudaGetSymbolAddress((void**)&keys_h4, g_keys_h4);
    uint4* ua_h4;    cudaGetSymbolAddress((void**)&ua_h4, g_ua_h4);
    uint4* wa_h4;    cudaGetSymbolAddress((void**)&wa_h4, g_wa_h4);

    cudaFuncSetAttribute(gemm_score_kernel, cudaFuncAttributeMaxDynamicSharedMemorySize, SMEM_BYTES);

    // converters: each thread handles 4 float4 -> 2 uint4
    cvt_kernel<<<(size_t)BSR * ND / 16 / 256, 256>>>((const float4*)keys, keys_h4);
    cvt_kernel<<<ND * ND / 16 / 256, 256>>>((const float4*)Ua_w, ua_h4);
    cvt_kernel<<<ND * ND / 16 / 256, 256>>>((const float4*)Wa_w, wa_h4);
    qw_kernel<<<dim3(NB, 8), 128>>>(query, Wa_b, Ua_b);
    gemm_score_kernel<<<dim3(NT_N, BSR / T_M), 128, SMEM_BYTES>>>(Va_w);
    softmax_kernel<<<NB, 256>>>(wts);
    ctx_part_kernel<<<dim3(NB, 4, 8), 128>>>(wts);
    ctx_reduce_kernel<<<NB, 1024>>>(ctx);
}